// round 1
// baseline (speedup 1.0000x reference)
#include <cuda_runtime.h>

#define N_STU   10000
#define N_ITEM  50000
#define N_CONC  2048
#define EDGES   250000
#define KC      4
#define EMB     64
#define CNUM    128

// Scratch tables (static device globals: allocation-free).
__device__ float g_stu_proj [N_STU  * CNUM];   //  5.12 MB
__device__ float g_item_proj[N_ITEM * CNUM];   // 25.6  MB
__device__ float g_conc_stu [N_CONC * CNUM];   //  1.0  MB
__device__ float g_conc_item[N_CONC * CNUM];   //  1.0  MB

// out[row, c] = sum_e fusion[row, e] * W[c, col_off + e],  c in [0,128), e in [0,64)
__global__ __launch_bounds__(128)
void proj_kernel(const float* __restrict__ fusion,
                 const float* __restrict__ W,
                 int col_off, int nrows,
                 float* __restrict__ out)
{
    __shared__ float Wt [EMB][CNUM + 1];   // Wt[e][c], padded vs bank conflicts
    __shared__ float Fsm[32][EMB + 1];     // 32 fusion rows

    const int c = threadIdx.x;

    // Stage W half transposed: Wt[e][c] = W[c*128 + col_off + e]
    #pragma unroll
    for (int idx = c; idx < CNUM * EMB; idx += 128) {
        int cc = idx >> 6;
        int e  = idx & 63;
        Wt[e][cc] = W[cc * (2 * EMB) + col_off + e];
    }

    const int row0 = blockIdx.x * 32;
    #pragma unroll
    for (int idx = c; idx < 32 * EMB; idx += 128) {
        int r = idx >> 6;
        int e = idx & 63;
        int row = row0 + r;
        Fsm[r][e] = (row < nrows) ? fusion[row * EMB + e] : 0.0f;
    }
    __syncthreads();

    #pragma unroll
    for (int rg = 0; rg < 32; rg += 8) {
        float acc[8];
        #pragma unroll
        for (int j = 0; j < 8; j++) acc[j] = 0.0f;

        #pragma unroll
        for (int e = 0; e < EMB; e++) {
            float w = Wt[e][c];
            #pragma unroll
            for (int j = 0; j < 8; j++)
                acc[j] = fmaf(w, Fsm[rg + j][e], acc[j]);
        }
        #pragma unroll
        for (int j = 0; j < 8; j++) {
            int row = row0 + rg + j;
            if (row < nrows) out[row * CNUM + c] = acc[j];
        }
    }
}

__device__ __forceinline__ float sigf(float x)
{
    // 2 MUFU: EX2 (via __expf) + RCP (via __fdividef)
    return __fdividef(1.0f, 1.0f + __expf(-x));
}

// One warp per edge. Lane owns channels [4*lane, 4*lane+4).
__global__ __launch_bounds__(256)
void edge_kernel(const int*   __restrict__ stu_idx,
                 const int*   __restrict__ item_idx,
                 const int*   __restrict__ conc_idx,
                 const float* __restrict__ w_pred,
                 const float* __restrict__ b_pred,
                 float*       __restrict__ out)
{
    const int lane = threadIdx.x & 31;
    const int e    = blockIdx.x * 8 + (threadIdx.x >> 5);
    if (e >= EDGES) return;   // grid covers EDGES exactly (250000 = 31250*8)

    const int  s  = __ldg(stu_idx  + e);
    const int  it = __ldg(item_idx + e);
    const int4 q4 = __ldg(reinterpret_cast<const int4*>(conc_idx) + e);
    const float4 w4 = __ldg(reinterpret_cast<const float4*>(w_pred) + lane);
    const float  b  = __ldg(b_pred);

    const float4 s4 = __ldg(reinterpret_cast<const float4*>(g_stu_proj)  + s  * 32 + lane);
    const float4 i4 = __ldg(reinterpret_cast<const float4*>(g_item_proj) + it * 32 + lane);

    int qs[KC] = {q4.x, q4.y, q4.z, q4.w};
    float4 cs[KC], ci[KC];
    // Issue all gathers up-front for MLP.
    #pragma unroll
    for (int k = 0; k < KC; k++) {
        cs[k] = __ldg(reinterpret_cast<const float4*>(g_conc_stu)  + qs[k] * 32 + lane);
        ci[k] = __ldg(reinterpret_cast<const float4*>(g_conc_item) + qs[k] * 32 + lane);
    }

    float total = 0.0f;
    #pragma unroll
    for (int k = 0; k < KC; k++) {
        float acc;
        acc  = w4.x * (sigf(s4.x + cs[k].x) - sigf(i4.x + ci[k].x));
        acc += w4.y * (sigf(s4.y + cs[k].y) - sigf(i4.y + ci[k].y));
        acc += w4.z * (sigf(s4.z + cs[k].z) - sigf(i4.z + ci[k].z));
        acc += w4.w * (sigf(s4.w + cs[k].w) - sigf(i4.w + ci[k].w));
        #pragma unroll
        for (int off = 16; off; off >>= 1)
            acc += __shfl_xor_sync(0xFFFFFFFFu, acc, off);
        total += sigf(acc + b);
    }
    if (lane == 0) out[e] = total * 0.25f;
}

extern "C" void kernel_launch(void* const* d_in, const int* in_sizes, int n_in,
                              void* d_out, int out_size)
{
    const int*   stu_idx        = (const int*)  d_in[0];
    const int*   item_idx       = (const int*)  d_in[1];
    const int*   conc_idx       = (const int*)  d_in[2];
    const float* stu_fusion     = (const float*)d_in[3];
    const float* item_fusion    = (const float*)d_in[4];
    const float* concept_fusion = (const float*)d_in[5];
    const float* W_stu          = (const float*)d_in[6];
    const float* W_item         = (const float*)d_in[7];
    const float* w_pred         = (const float*)d_in[8];
    const float* b_pred         = (const float*)d_in[9];
    float*       out            = (float*)d_out;

    float *p_sp, *p_ip, *p_cs, *p_ci;
    cudaGetSymbolAddress((void**)&p_sp, g_stu_proj);
    cudaGetSymbolAddress((void**)&p_ip, g_item_proj);
    cudaGetSymbolAddress((void**)&p_cs, g_conc_stu);
    cudaGetSymbolAddress((void**)&p_ci, g_conc_item);

    proj_kernel<<<(N_STU  + 31) / 32, 128>>>(stu_fusion,     W_stu,  0,   N_STU,  p_sp);
    proj_kernel<<<(N_ITEM + 31) / 32, 128>>>(item_fusion,    W_item, 0,   N_ITEM, p_ip);
    proj_kernel<<<(N_CONC + 31) / 32, 128>>>(concept_fusion, W_stu,  EMB, N_CONC, p_cs);
    proj_kernel<<<(N_CONC + 31) / 32, 128>>>(concept_fusion, W_item, EMB, N_CONC, p_ci);

    edge_kernel<<<EDGES / 8, 256>>>(stu_idx, item_idx, conc_idx, w_pred, b_pred, out);
}

// round 4
// speedup vs baseline: 1.3150x; 1.3150x over previous
#include <cuda_runtime.h>
#include <cuda_fp16.h>

#define N_STU   10000
#define N_ITEM  50000
#define N_CONC  2048
#define EDGES   250000
#define KC      4
#define EMB     64
#define CNUM    128

#define B_STU   313     // ceil(10000/32)
#define B_ITEM  1563    // ceil(50000/32)
#define B_CONC  64      // 2048/32

// fp16 tables, values pre-multiplied by 0.5 (for the tanh half-angle form).
__device__ __half g_stu_proj [N_STU  * CNUM];   //  2.56 MB
__device__ __half g_item_proj[N_ITEM * CNUM];   // 12.8  MB
__device__ __half g_conc_stu [N_CONC * CNUM];   //  0.5  MB
__device__ __half g_conc_item[N_CONC * CNUM];   //  0.5  MB

namespace {

__device__ __forceinline__ __half2 dg_tanh2(__half2 x)
{
    unsigned r, xi = *reinterpret_cast<unsigned*>(&x);
    asm("tanh.approx.f16x2 %0, %1;" : "=r"(r) : "r"(xi));
    return *reinterpret_cast<__half2*>(&r);
}

__device__ __forceinline__ float dg_sigmoid(float x)
{
    return __fdividef(1.0f, 1.0f + __expf(-x));
}

// Computes out_half[row, c] = 0.5 * sum_e fusion[row, e] * W[c, col_off + e]
__device__ __forceinline__
void proj_tile(const float* __restrict__ fusion,
               const float* __restrict__ W,
               int col_off, int nrows, int row0,
               __half* __restrict__ out)
{
    __shared__ float Wt [EMB][CNUM + 1];
    __shared__ float Fsm[32][EMB + 1];

    const int c = threadIdx.x;

    #pragma unroll
    for (int idx = c; idx < CNUM * EMB; idx += 128) {
        int cc = idx >> 6;
        int e  = idx & 63;
        Wt[e][cc] = W[cc * (2 * EMB) + col_off + e];
    }
    #pragma unroll
    for (int idx = c; idx < 32 * EMB; idx += 128) {
        int r = idx >> 6;
        int e = idx & 63;
        int row = row0 + r;
        Fsm[r][e] = (row < nrows) ? fusion[row * EMB + e] : 0.0f;
    }
    __syncthreads();

    #pragma unroll
    for (int rg = 0; rg < 32; rg += 8) {
        float acc[8];
        #pragma unroll
        for (int j = 0; j < 8; j++) acc[j] = 0.0f;

        #pragma unroll
        for (int e = 0; e < EMB; e++) {
            float w = Wt[e][c];
            #pragma unroll
            for (int j = 0; j < 8; j++)
                acc[j] = fmaf(w, Fsm[rg + j][e], acc[j]);
        }
        #pragma unroll
        for (int j = 0; j < 8; j++) {
            int row = row0 + rg + j;
            if (row < nrows) out[row * CNUM + c] = __float2half(acc[j] * 0.5f);
        }
    }
}

} // anonymous namespace

// All four projections in one launch.
__global__ __launch_bounds__(128)
void proj_all(const float* __restrict__ stu_fusion,
              const float* __restrict__ item_fusion,
              const float* __restrict__ conc_fusion,
              const float* __restrict__ W_stu,
              const float* __restrict__ W_item,
              __half* p_sp, __half* p_ip, __half* p_cs, __half* p_ci)
{
    int b = blockIdx.x;
    if (b < B_STU) {
        proj_tile(stu_fusion, W_stu, 0, N_STU, b * 32, p_sp);
    } else if (b < B_STU + B_ITEM) {
        proj_tile(item_fusion, W_item, 0, N_ITEM, (b - B_STU) * 32, p_ip);
    } else if (b < B_STU + B_ITEM + B_CONC) {
        proj_tile(conc_fusion, W_stu, EMB, N_CONC, (b - B_STU - B_ITEM) * 32, p_cs);
    } else {
        proj_tile(conc_fusion, W_item, EMB, N_CONC, (b - B_STU - B_ITEM - B_CONC) * 32, p_ci);
    }
}

// One warp per edge. Lane owns channels [4*lane, 4*lane+4) as two half2.
// Tables hold 0.5*value, so (s + c) is already x/2: sig(x) = 0.5*(1 + tanh(x/2)).
// diff of sigmoids = 0.5*(tanh_s - tanh_i); the 0.5 is folded into w.
__global__ __launch_bounds__(256)
void edge_kernel(const int*   __restrict__ stu_idx,
                 const int*   __restrict__ item_idx,
                 const int*   __restrict__ conc_idx,
                 const float* __restrict__ w_pred,
                 const float* __restrict__ b_pred,
                 float*       __restrict__ out)
{
    const int lane = threadIdx.x & 31;
    const int e    = blockIdx.x * 8 + (threadIdx.x >> 5);

    const int  s  = __ldg(stu_idx  + e);
    const int  it = __ldg(item_idx + e);
    const int4 q4 = __ldg(reinterpret_cast<const int4*>(conc_idx) + e);
    const float4 w4 = __ldg(reinterpret_cast<const float4*>(w_pred) + lane);
    const float  b  = __ldg(b_pred);

    const __half2 wa = __floats2half2_rn(0.5f * w4.x, 0.5f * w4.y);
    const __half2 wb = __floats2half2_rn(0.5f * w4.z, 0.5f * w4.w);

    const uint2 sraw = __ldg(reinterpret_cast<const uint2*>(g_stu_proj)  + s  * 32 + lane);
    const uint2 iraw = __ldg(reinterpret_cast<const uint2*>(g_item_proj) + it * 32 + lane);

    int qs[KC] = {q4.x, q4.y, q4.z, q4.w};
    uint2 cs[KC], ci[KC];
    #pragma unroll
    for (int k = 0; k < KC; k++) {
        cs[k] = __ldg(reinterpret_cast<const uint2*>(g_conc_stu)  + qs[k] * 32 + lane);
        ci[k] = __ldg(reinterpret_cast<const uint2*>(g_conc_item) + qs[k] * 32 + lane);
    }

    const __half2 sa = *reinterpret_cast<const __half2*>(&sraw.x);
    const __half2 sb = *reinterpret_cast<const __half2*>(&sraw.y);
    const __half2 ia = *reinterpret_cast<const __half2*>(&iraw.x);
    const __half2 ib = *reinterpret_cast<const __half2*>(&iraw.y);

    float total = 0.0f;
    #pragma unroll
    for (int k = 0; k < KC; k++) {
        __half2 csa = *reinterpret_cast<const __half2*>(&cs[k].x);
        __half2 csb = *reinterpret_cast<const __half2*>(&cs[k].y);
        __half2 cia = *reinterpret_cast<const __half2*>(&ci[k].x);
        __half2 cib = *reinterpret_cast<const __half2*>(&ci[k].y);

        __half2 ts_a = dg_tanh2(__hadd2(sa, csa));
        __half2 ts_b = dg_tanh2(__hadd2(sb, csb));
        __half2 ti_a = dg_tanh2(__hadd2(ia, cia));
        __half2 ti_b = dg_tanh2(__hadd2(ib, cib));

        __half2 acc2 = __hmul2(__hsub2(ts_a, ti_a), wa);
        acc2 = __hfma2(__hsub2(ts_b, ti_b), wb, acc2);

        float2 f = __half22float2(acc2);
        float acc = f.x + f.y;
        #pragma unroll
        for (int off = 16; off; off >>= 1)
            acc += __shfl_xor_sync(0xFFFFFFFFu, acc, off);
        total += dg_sigmoid(acc + b);
    }
    if (lane == 0) out[e] = total * 0.25f;
}

extern "C" void kernel_launch(void* const* d_in, const int* in_sizes, int n_in,
                              void* d_out, int out_size)
{
    const int*   stu_idx        = (const int*)  d_in[0];
    const int*   item_idx       = (const int*)  d_in[1];
    const int*   conc_idx       = (const int*)  d_in[2];
    const float* stu_fusion     = (const float*)d_in[3];
    const float* item_fusion    = (const float*)d_in[4];
    const float* concept_fusion = (const float*)d_in[5];
    const float* W_stu          = (const float*)d_in[6];
    const float* W_item         = (const float*)d_in[7];
    const float* w_pred         = (const float*)d_in[8];
    const float* b_pred         = (const float*)d_in[9];
    float*       out            = (float*)d_out;

    __half *p_sp, *p_ip, *p_cs, *p_ci;
    cudaGetSymbolAddress((void**)&p_sp, g_stu_proj);
    cudaGetSymbolAddress((void**)&p_ip, g_item_proj);
    cudaGetSymbolAddress((void**)&p_cs, g_conc_stu);
    cudaGetSymbolAddress((void**)&p_ci, g_conc_item);

    proj_all<<<B_STU + B_ITEM + 2 * B_CONC, 128>>>(
        stu_fusion, item_fusion, concept_fusion, W_stu, W_item,
        p_sp, p_ip, p_cs, p_ci);

    edge_kernel<<<EDGES / 8, 256>>>(stu_idx, item_idx, conc_idx, w_pred, b_pred, out);
}

// round 5
// speedup vs baseline: 1.7959x; 1.3657x over previous
#include <cuda_runtime.h>
#include <cuda_fp16.h>

#define N_STU   10000
#define N_ITEM  50000
#define N_CONC  2048
#define EDGES   250000
#define KC      4
#define EMB     64
#define CNUM    128

#define PB_STU   313     // ceil(10000/32)
#define PB_ITEM  1563    // ceil(50000/32)
#define PB_CONC  64      // 2048/32

// fp16 tables, values pre-multiplied by 0.5 (for the tanh half-angle form).
__device__ __half g_stu_proj [N_STU  * CNUM];   //  2.56 MB
__device__ __half g_item_proj[N_ITEM * CNUM];   // 12.8  MB
__device__ __half g_conc_stu [N_CONC * CNUM];   //  0.5  MB
__device__ __half g_conc_item[N_CONC * CNUM];   //  0.5  MB

namespace {

__device__ __forceinline__ __half2 dg_tanh2(__half2 x)
{
    unsigned r, xi = *reinterpret_cast<unsigned*>(&x);
    asm("tanh.approx.f16x2 %0, %1;" : "=r"(r) : "r"(xi));
    return *reinterpret_cast<__half2*>(&r);
}

__device__ __forceinline__ float dg_sigmoid(float x)
{
    return __fdividef(1.0f, 1.0f + __expf(-x));
}

__device__ __forceinline__ unsigned dg_tf32(float f)
{
    unsigned r;
    asm("cvt.rna.tf32.f32 %0, %1;" : "=r"(r) : "f"(f));
    return r;
}

__device__ __forceinline__ void dg_mma(float d[4],
                                       unsigned a0, unsigned a1, unsigned a2, unsigned a3,
                                       unsigned b0, unsigned b1)
{
    asm volatile(
        "mma.sync.aligned.m16n8k8.row.col.f32.tf32.tf32.f32 "
        "{%0,%1,%2,%3}, {%4,%5,%6,%7}, {%8,%9}, {%0,%1,%2,%3};"
        : "+f"(d[0]), "+f"(d[1]), "+f"(d[2]), "+f"(d[3])
        : "r"(a0), "r"(a1), "r"(a2), "r"(a3), "r"(b0), "r"(b1));
}

// Tensor-core tile: out_half[row, c] = 0.5 * sum_e fusion[row, e] * W[c, col_off + e]
// Block: 32 rows x 128 cols, 256 threads = 8 warps (2 m-tiles x 4 n-strips of 32).
__device__ __forceinline__
void proj_tile(const float* __restrict__ fusion,
               const float* __restrict__ W,
               int col_off, int nrows, int row0,
               __half* __restrict__ out)
{
    // stride 68: 68 mod 32 == 4 -> fragment banks = 4*(lane/4) + lane%4, all distinct
    __shared__ unsigned Fsm[32][68];     // F[r][e], tf32
    __shared__ unsigned Wsm[CNUM][68];   // W[c][e], tf32

    const int tid = threadIdx.x;

    for (int idx = tid; idx < CNUM * EMB; idx += 256) {
        int c = idx >> 6;
        int e = idx & 63;
        Wsm[c][e] = dg_tf32(W[c * (2 * EMB) + col_off + e]);
    }
    for (int idx = tid; idx < 32 * EMB; idx += 256) {
        int r = idx >> 6;
        int e = idx & 63;
        int row = row0 + r;
        Fsm[r][e] = dg_tf32((row < nrows) ? fusion[row * EMB + e] : 0.0f);
    }
    __syncthreads();

    const int warp = tid >> 5;
    const int lane = tid & 31;
    const int qr   = lane >> 2;   // 0..7
    const int qc   = lane & 3;    // 0..3

    const int r0 = (warp & 1) * 16;        // m-tile
    const int n0 = (warp >> 1) * 32;       // n-strip

    float d[4][4];
    #pragma unroll
    for (int nt = 0; nt < 4; nt++)
        #pragma unroll
        for (int j = 0; j < 4; j++) d[nt][j] = 0.0f;

    #pragma unroll
    for (int ks = 0; ks < 8; ks++) {
        const int k0 = ks * 8;
        unsigned a0 = Fsm[r0 + qr    ][k0 + qc    ];
        unsigned a1 = Fsm[r0 + qr + 8][k0 + qc    ];
        unsigned a2 = Fsm[r0 + qr    ][k0 + qc + 4];
        unsigned a3 = Fsm[r0 + qr + 8][k0 + qc + 4];
        #pragma unroll
        for (int nt = 0; nt < 4; nt++) {
            const int n = n0 + nt * 8;
            unsigned b0 = Wsm[n + qr][k0 + qc    ];
            unsigned b1 = Wsm[n + qr][k0 + qc + 4];
            dg_mma(d[nt], a0, a1, a2, a3, b0, b1);
        }
    }

    #pragma unroll
    for (int nt = 0; nt < 4; nt++) {
        const int col = n0 + nt * 8 + qc * 2;
        int row = row0 + r0 + qr;
        if (row < nrows)
            *reinterpret_cast<__half2*>(out + row * CNUM + col) =
                __floats2half2_rn(d[nt][0] * 0.5f, d[nt][1] * 0.5f);
        row += 8;
        if (row < nrows)
            *reinterpret_cast<__half2*>(out + row * CNUM + col) =
                __floats2half2_rn(d[nt][2] * 0.5f, d[nt][3] * 0.5f);
    }
}

} // anonymous namespace

// All four projections in one launch.
__global__ __launch_bounds__(256)
void proj_all(const float* __restrict__ stu_fusion,
              const float* __restrict__ item_fusion,
              const float* __restrict__ conc_fusion,
              const float* __restrict__ W_stu,
              const float* __restrict__ W_item,
              __half* p_sp, __half* p_ip, __half* p_cs, __half* p_ci)
{
    int b = blockIdx.x;
    if (b < PB_STU) {
        proj_tile(stu_fusion, W_stu, 0, N_STU, b * 32, p_sp);
    } else if (b < PB_STU + PB_ITEM) {
        proj_tile(item_fusion, W_item, 0, N_ITEM, (b - PB_STU) * 32, p_ip);
    } else if (b < PB_STU + PB_ITEM + PB_CONC) {
        proj_tile(conc_fusion, W_stu, EMB, N_CONC, (b - PB_STU - PB_ITEM) * 32, p_cs);
    } else {
        proj_tile(conc_fusion, W_item, EMB, N_CONC, (b - PB_STU - PB_ITEM - PB_CONC) * 32, p_ci);
    }
}

// One warp per edge. Lane owns channels [4*lane, 4*lane+4) as two half2.
// Tables hold 0.5*value, so (s + c) is already x/2: sig(x) = 0.5*(1 + tanh(x/2)).
// diff of sigmoids = 0.5*(tanh_s - tanh_i); the 0.5 is folded into w.
__global__ __launch_bounds__(256)
void edge_kernel(const int*   __restrict__ stu_idx,
                 const int*   __restrict__ item_idx,
                 const int*   __restrict__ conc_idx,
                 const float* __restrict__ w_pred,
                 const float* __restrict__ b_pred,
                 float*       __restrict__ out)
{
    const int lane = threadIdx.x & 31;
    const int e    = blockIdx.x * 8 + (threadIdx.x >> 5);

    const int  s  = __ldg(stu_idx  + e);
    const int  it = __ldg(item_idx + e);
    const int4 q4 = __ldg(reinterpret_cast<const int4*>(conc_idx) + e);
    const float4 w4 = __ldg(reinterpret_cast<const float4*>(w_pred) + lane);
    const float  b  = __ldg(b_pred);

    const __half2 wa = __floats2half2_rn(0.5f * w4.x, 0.5f * w4.y);
    const __half2 wb = __floats2half2_rn(0.5f * w4.z, 0.5f * w4.w);

    const uint2 sraw = __ldg(reinterpret_cast<const uint2*>(g_stu_proj)  + s  * 32 + lane);
    const uint2 iraw = __ldg(reinterpret_cast<const uint2*>(g_item_proj) + it * 32 + lane);

    int qs[KC] = {q4.x, q4.y, q4.z, q4.w};
    uint2 cs[KC], ci[KC];
    #pragma unroll
    for (int k = 0; k < KC; k++) {
        cs[k] = __ldg(reinterpret_cast<const uint2*>(g_conc_stu)  + qs[k] * 32 + lane);
        ci[k] = __ldg(reinterpret_cast<const uint2*>(g_conc_item) + qs[k] * 32 + lane);
    }

    const __half2 sa = *reinterpret_cast<const __half2*>(&sraw.x);
    const __half2 sb = *reinterpret_cast<const __half2*>(&sraw.y);
    const __half2 ia = *reinterpret_cast<const __half2*>(&iraw.x);
    const __half2 ib = *reinterpret_cast<const __half2*>(&iraw.y);

    float total = 0.0f;
    #pragma unroll
    for (int k = 0; k < KC; k++) {
        __half2 csa = *reinterpret_cast<const __half2*>(&cs[k].x);
        __half2 csb = *reinterpret_cast<const __half2*>(&cs[k].y);
        __half2 cia = *reinterpret_cast<const __half2*>(&ci[k].x);
        __half2 cib = *reinterpret_cast<const __half2*>(&ci[k].y);

        __half2 ts_a = dg_tanh2(__hadd2(sa, csa));
        __half2 ts_b = dg_tanh2(__hadd2(sb, csb));
        __half2 ti_a = dg_tanh2(__hadd2(ia, cia));
        __half2 ti_b = dg_tanh2(__hadd2(ib, cib));

        __half2 acc2 = __hmul2(__hsub2(ts_a, ti_a), wa);
        acc2 = __hfma2(__hsub2(ts_b, ti_b), wb, acc2);

        float2 f = __half22float2(acc2);
        float acc = f.x + f.y;
        #pragma unroll
        for (int off = 16; off; off >>= 1)
            acc += __shfl_xor_sync(0xFFFFFFFFu, acc, off);
        total += dg_sigmoid(acc + b);
    }
    if (lane == 0) out[e] = total * 0.25f;
}

extern "C" void kernel_launch(void* const* d_in, const int* in_sizes, int n_in,
                              void* d_out, int out_size)
{
    const int*   stu_idx        = (const int*)  d_in[0];
    const int*   item_idx       = (const int*)  d_in[1];
    const int*   conc_idx       = (const int*)  d_in[2];
    const float* stu_fusion     = (const float*)d_in[3];
    const float* item_fusion    = (const float*)d_in[4];
    const float* concept_fusion = (const float*)d_in[5];
    const float* W_stu          = (const float*)d_in[6];
    const float* W_item         = (const float*)d_in[7];
    const float* w_pred         = (const float*)d_in[8];
    const float* b_pred         = (const float*)d_in[9];
    float*       out            = (float*)d_out;

    __half *p_sp, *p_ip, *p_cs, *p_ci;
    cudaGetSymbolAddress((void**)&p_sp, g_stu_proj);
    cudaGetSymbolAddress((void**)&p_ip, g_item_proj);
    cudaGetSymbolAddress((void**)&p_cs, g_conc_stu);
    cudaGetSymbolAddress((void**)&p_ci, g_conc_item);

    proj_all<<<PB_STU + PB_ITEM + 2 * PB_CONC, 256>>>(
        stu_fusion, item_fusion, concept_fusion, W_stu, W_item,
        p_sp, p_ip, p_cs, p_ci);

    edge_kernel<<<EDGES / 8, 256>>>(stu_idx, item_idx, conc_idx, w_pred, b_pred, out);
}